// round 13
// baseline (speedup 1.0000x reference)
#include <cuda_runtime.h>
#include <cuda_fp16.h>
#include <math.h>
#include <stdint.h>

// Problem constants
#define BB       4
#define NN       16384
#define DD       512
#define HH       8
#define DK       64
#define DV       64
#define HID      2048
#define NTOK     (BB * NN)          // 65536
#define LN_EPS   1e-5f
#define ATTN_EPS 1e-6f

// ---------------------------------------------------------------------------
// Scratch (device globals — no allocation allowed)
// ---------------------------------------------------------------------------
__device__ __half g_h   [(size_t)NTOK * DD];
__device__ __half g_pq  [(size_t)NTOK * DD];
__device__ __half g_pk  [(size_t)NTOK * DD];
__device__ __half g_v   [(size_t)NTOK * DD];
__device__ __half g_attn[(size_t)NTOK * DD];
__device__ __half g_hres[(size_t)NTOK * DD];
__device__ __half g_h2  [(size_t)NTOK * DD];
__device__ __half g_act [(size_t)NTOK * HID];
__device__ float  g_kv  [BB * HH * DK * DV];
__device__ float  g_ksum[BB * HH * DK];
__device__ __half g_wqkvt[3 * DD * DD];
__device__ __half g_wot[DD * DD];
__device__ __half g_w1t[(size_t)HID * DD];
__device__ __half g_w2t[(size_t)DD * HID];
__device__ float  g_bqkv[3 * DD];

// ---------------------------------------------------------------------------
// helpers
// ---------------------------------------------------------------------------
__device__ __forceinline__ uint32_t smem_u32(const void* p) {
    uint32_t a;
    asm("{ .reg .u64 t; cvta.to.shared.u64 t, %1; cvt.u32.u64 %0, t; }" : "=r"(a) : "l"(p));
    return a;
}

#define CP_ASYNC16(dst_u32, src) \
    asm volatile("cp.async.cg.shared.global [%0], [%1], 16;" :: "r"(dst_u32), "l"(src))
#define CP_COMMIT() asm volatile("cp.async.commit_group;" ::: "memory")
#define CP_WAIT(n)  asm volatile("cp.async.wait_group %0;" :: "n"(n) : "memory")

#define LDSM_X4(r0, r1, r2, r3, addr) \
    asm volatile("ldmatrix.sync.aligned.m8n8.x4.shared.b16 {%0,%1,%2,%3}, [%4];" \
        : "=r"(r0), "=r"(r1), "=r"(r2), "=r"(r3) : "r"(addr))
#define LDSM_X4T(r0, r1, r2, r3, addr) \
    asm volatile("ldmatrix.sync.aligned.m8n8.x4.trans.shared.b16 {%0,%1,%2,%3}, [%4];" \
        : "=r"(r0), "=r"(r1), "=r"(r2), "=r"(r3) : "r"(addr))

__device__ __forceinline__ void mma_f16_16n8k16(float c[4], uint32_t a0, uint32_t a1,
                                                uint32_t a2, uint32_t a3,
                                                uint32_t b0, uint32_t b1)
{
    asm volatile(
        "mma.sync.aligned.m16n8k16.row.col.f32.f16.f16.f32 "
        "{%0,%1,%2,%3}, {%4,%5,%6,%7}, {%8,%9}, {%0,%1,%2,%3};"
        : "+f"(c[0]), "+f"(c[1]), "+f"(c[2]), "+f"(c[3])
        : "r"(a0), "r"(a1), "r"(a2), "r"(a3), "r"(b0), "r"(b1));
}

// ---------------------------------------------------------------------------
// fp16 GEMM (R12 skeleton + ldmatrix fragment loads):
// tile 128x128, BK=64, 3-stage cp.async (1 sync/kt), 8 warps 2Mx4N,
// double-buffered LDSM fragments (precomputed lane offsets), 2 CTAs/SM
// ---------------------------------------------------------------------------
#define EPI_QKV  0
#define EPI_GELU 2
#define EPI_RES  3

#define BM      128
#define BN      128
#define BK      64
#define PADK    72
#define SA_H    (BM * PADK)
#define STG_H   (2 * SA_H)
#define NSTG    3
#define GEMM_SMEM (NSTG * STG_H * 2)     // 110592 bytes

__device__ __forceinline__ float gelu_tanh(float x) {
    float x3 = x * x * x;
    return 0.5f * x * (1.0f + tanhf(0.7978845608028654f * (x + 0.044715f * x3)));
}

template<int EPI, typename CT>
__global__ __launch_bounds__(256)
void mgemm_kernel(const __half* __restrict__ A, const __half* __restrict__ Bt,
                  const float* __restrict__ bias, const __half* __restrict__ resid,
                  CT* __restrict__ C, __half* __restrict__ C2, __half* __restrict__ C3,
                  int N, int K)
{
    extern __shared__ __half smem_h[];

    const int tid  = threadIdx.x;
    const int lane = tid & 31;
    const int wid  = tid >> 5;
    const int warpM = wid & 1;
    const int warpN = wid >> 1;

    const int mbase = blockIdx.y * BM;
    const int nbase = blockIdx.x * BN;

    const uint32_t s_u = smem_u32(smem_h);

    float acc[4][4][4];
    #pragma unroll
    for (int i = 0; i < 4; i++)
        #pragma unroll
        for (int j = 0; j < 4; j++)
            #pragma unroll
            for (int r = 0; r < 4; r++) acc[i][j][r] = 0.0f;

    const int T = K / BK;

    auto load_stage = [&](int kt, int st) {
        const int k0 = kt * BK;
        const uint32_t base = s_u + (uint32_t)(st * STG_H * 2);
        #pragma unroll
        for (int i = 0; i < 4; i++) {
            int linear = tid + i * 256;
            int row = linear >> 3;
            int col = (linear & 7) * 8;
            CP_ASYNC16(base + (uint32_t)((row * PADK + col) * 2),
                       A + (size_t)(mbase + row) * K + k0 + col);
            CP_ASYNC16(base + (uint32_t)((SA_H + row * PADK + col) * 2),
                       Bt + (size_t)(nbase + row) * K + k0 + col);
        }
    };

    load_stage(0, 0); CP_COMMIT();
    load_stage(1, 1); CP_COMMIT();

    const int q = lane >> 2, r4 = lane & 3;
    // ldmatrix lane addressing (precomputed byte offsets relative to stage base)
    const int lrow = lane & 15;
    const uint32_t lk8b = (uint32_t)(((lane >> 4) << 3) * 2);
    const uint32_t aoff0 = (uint32_t)(((warpM * 64 + lrow) * PADK) * 2) + lk8b;
    const uint32_t boff0 = (uint32_t)((SA_H + (warpN * 32 + lrow) * PADK) * 2) + lk8b;

    for (int kt = 0; kt < T; kt++) {
        CP_WAIT(1);
        __syncthreads();                 // stage kt%3 visible; kt-1 consumed last iter

        if (kt + 2 < T) load_stage(kt + 2, (kt + 2) % NSTG);
        CP_COMMIT();

        const uint32_t st_u = s_u + (uint32_t)((kt % NSTG) * STG_H * 2);

        uint32_t afr[2][4][4];
        uint32_t bfr[2][2][4];           // [buf][p][m0even,m1odd,k8even,k8odd]

        auto load_frag = [&](int ks, int buf) {
            const uint32_t kkb = (uint32_t)(ks * 32);
            #pragma unroll
            for (int mt = 0; mt < 4; mt++)
                LDSM_X4(afr[buf][mt][0], afr[buf][mt][1], afr[buf][mt][2], afr[buf][mt][3],
                        st_u + aoff0 + (uint32_t)(mt * 16 * PADK * 2) + kkb);
            #pragma unroll
            for (int p = 0; p < 2; p++)
                LDSM_X4(bfr[buf][p][0], bfr[buf][p][1], bfr[buf][p][2], bfr[buf][p][3],
                        st_u + boff0 + (uint32_t)(p * 16 * PADK * 2) + kkb);
        };

        load_frag(0, 0);
        #pragma unroll
        for (int ks = 0; ks < 4; ks++) {
            if (ks < 3) load_frag(ks + 1, (ks + 1) & 1);
            const int b = ks & 1;
            #pragma unroll
            for (int mt = 0; mt < 4; mt++) {
                #pragma unroll
                for (int p = 0; p < 2; p++) {
                    mma_f16_16n8k16(acc[mt][2 * p],     afr[b][mt][0], afr[b][mt][1],
                                    afr[b][mt][2], afr[b][mt][3],
                                    bfr[b][p][0], bfr[b][p][2]);
                    mma_f16_16n8k16(acc[mt][2 * p + 1], afr[b][mt][0], afr[b][mt][1],
                                    afr[b][mt][2], afr[b][mt][3],
                                    bfr[b][p][1], bfr[b][p][3]);
                }
            }
        }
    }

    __half* qdst = nullptr;
    int ldc = N, cadj = 0;
    bool do_phi = false;
    if (EPI == EPI_QKV) {
        int sector = nbase >> 9;
        qdst = (sector == 0) ? (__half*)C : (sector == 1) ? C2 : C3;
        ldc = DD;
        cadj = sector << 9;
        do_phi = (sector < 2);
    }

    #pragma unroll
    for (int mt = 0; mt < 4; mt++) {
        #pragma unroll
        for (int nt = 0; nt < 4; nt++) {
            int col = nbase + warpN * 32 + nt * 8 + 2 * r4;
            float2 bv = *(const float2*)(bias + col);
            #pragma unroll
            for (int half_i = 0; half_i < 2; half_i++) {
                size_t row = (size_t)(mbase + warpM * 64 + mt * 16 + q + half_i * 8);
                float2 o;
                o.x = acc[mt][nt][half_i * 2 + 0] + bv.x;
                o.y = acc[mt][nt][half_i * 2 + 1] + bv.y;
                if (EPI == EPI_QKV) {
                    if (do_phi) {
                        o.x = (o.x > 0.0f) ? o.x + 1.0f : expf(o.x);
                        o.y = (o.y > 0.0f) ? o.y + 1.0f : expf(o.y);
                    }
                    *(__half2*)(qdst + row * ldc + (col - cadj)) = __floats2half2_rn(o.x, o.y);
                } else if (EPI == EPI_GELU) {
                    o.x = gelu_tanh(o.x);
                    o.y = gelu_tanh(o.y);
                    *(__half2*)((__half*)C + row * N + col) = __floats2half2_rn(o.x, o.y);
                } else { // EPI_RES
                    float2 rv = __half22float2(*(const __half2*)(resid + row * N + col));
                    o.x += rv.x; o.y += rv.y;
                    if (sizeof(CT) == 2)
                        *(__half2*)((__half*)C + row * N + col) = __floats2half2_rn(o.x, o.y);
                    else
                        *(float2*)((float*)C + row * N + col) = o;
                }
            }
        }
    }
}

// ---------------------------------------------------------------------------
// kvred via tensor cores (unchanged)
// ---------------------------------------------------------------------------
#define KVC       2048
#define KVSN      128
#define KVPAD     72
#define KV_SA     (KVSN * KVPAD)
#define KV_STG    (2 * KV_SA)
#define KV_NSTG   3
#define KVRED_SMEM (KV_NSTG * KV_STG * 2)

__global__ __launch_bounds__(256)
void kvred_mma_kernel(const __half* __restrict__ pk, const __half* __restrict__ v)
{
    extern __shared__ __half smem_h[];
    const int tid = threadIdx.x, lane = tid & 31, wid = tid >> 5;
    const int bh = blockIdx.x;
    const int b = bh >> 3, h = bh & 7;
    const int n0 = blockIdx.y * KVC;
    const uint32_t s_u = smem_u32(smem_h);

    const int d0 = (wid & 3) * 16;
    const int mhalf = (wid >> 2) * 32;

    float acc[4][4];
    #pragma unroll
    for (int i = 0; i < 4; i++)
        #pragma unroll
        for (int j = 0; j < 4; j++) acc[i][j] = 0.0f;
    float ks = 0.0f;

    const size_t gbase0 = ((size_t)b * NN + n0) * DD + h * 64;

    auto load_stage = [&](int s, int st) {
        const size_t gb = gbase0 + (size_t)s * KVSN * DD;
        const uint32_t sb = s_u + (uint32_t)(st * KV_STG * 2);
        #pragma unroll
        for (int i = 0; i < 8; i++) {
            int c = tid + i * 256;
            int arr = c >> 10;
            int row = (c >> 3) & 127;
            int col = (c & 7) * 8;
            const __half* src = (arr ? v : pk) + gb + (size_t)row * DD + col;
            CP_ASYNC16(sb + (uint32_t)((arr * KV_SA + row * KVPAD + col) * 2), src);
        }
    };

    load_stage(0, 0); CP_COMMIT();
    load_stage(1, 1); CP_COMMIT();

    const uint32_t a_loff = (uint32_t)(
        (((lane & 7) + ((lane >> 4) << 3)) * KVPAD + d0 + (((lane >> 3) & 1) << 3)) * 2);
    const uint32_t b_loff = (uint32_t)(
        (((lane & 7) + (((lane >> 3) & 1) << 3)) * KVPAD + mhalf + ((lane >> 4) << 3)) * 2);

    const int ksd = tid & 63, ksseg = tid >> 6;
    const int NSTAGES = KVC / KVSN;

    for (int s = 0; s < NSTAGES; s++) {
        CP_WAIT(1);
        __syncthreads();
        if (s + 2 < NSTAGES) load_stage(s + 2, (s + 2) % KV_NSTG);
        CP_COMMIT();

        const uint32_t pkb = s_u + (uint32_t)((s % KV_NSTG) * KV_STG * 2);
        const uint32_t vb  = pkb + (uint32_t)(KV_SA * 2);

        #pragma unroll
        for (int k16 = 0; k16 < KVSN / 16; k16++) {
            const uint32_t kofs = (uint32_t)(k16 * 16 * KVPAD * 2);
            uint32_t a0, a1, a2, a3;
            LDSM_X4T(a0, a1, a2, a3, pkb + kofs + a_loff);
            #pragma unroll
            for (int p = 0; p < 2; p++) {
                uint32_t r0, r1, r2, r3;
                LDSM_X4T(r0, r1, r2, r3, vb + kofs + b_loff + (uint32_t)(p * 32));
                mma_f16_16n8k16(acc[p * 2],     a0, a1, a2, a3, r0, r1);
                mma_f16_16n8k16(acc[p * 2 + 1], a0, a1, a2, a3, r2, r3);
            }
        }
        {
            const __half* pkp = smem_h + (s % KV_NSTG) * KV_STG
                              + (ksseg * 32) * KVPAD + ksd;
            #pragma unroll
            for (int r = 0; r < 32; r++)
                ks += __half2float(pkp[r * KVPAD]);
        }
    }

    const int q = lane >> 2, r4 = lane & 3;
    float* kvp = g_kv + (size_t)bh * 4096;
    #pragma unroll
    for (int nt = 0; nt < 4; nt++) {
        int m = mhalf + nt * 8 + 2 * r4;
        atomicAdd(&kvp[(d0 + q) * 64 + m],     acc[nt][0]);
        atomicAdd(&kvp[(d0 + q) * 64 + m + 1], acc[nt][1]);
        atomicAdd(&kvp[(d0 + q + 8) * 64 + m],     acc[nt][2]);
        atomicAdd(&kvp[(d0 + q + 8) * 64 + m + 1], acc[nt][3]);
    }
    atomicAdd(&g_ksum[bh * 64 + ksd], ks);
}

// ---------------------------------------------------------------------------
// attention apply via tensor cores (unchanged)
// ---------------------------------------------------------------------------
#define AT_TOK  128
#define ATPAD   72

__global__ __launch_bounds__(256)
void attn_mma_kernel(const __half* __restrict__ pq, __half* __restrict__ out)
{
    __shared__ __half spq[AT_TOK * ATPAD];
    __shared__ __half skvt[64 * ATPAD];
    __shared__ float sz[AT_TOK];
    __shared__ float sks[64];

    const int tid = threadIdx.x, lane = tid & 31, wid = tid >> 5;
    const int bh = blockIdx.y, b = bh >> 3, h = bh & 7;
    const int t0 = blockIdx.x * AT_TOK;
    const uint32_t spq_u = smem_u32(spq);
    const uint32_t skv_u = smem_u32(skvt);

    const size_t gq = ((size_t)b * NN + t0) * DD + h * 64;
    #pragma unroll
    for (int i = 0; i < 4; i++) {
        int c = tid + i * 256;
        int row = c >> 3, col = (c & 7) * 8;
        CP_ASYNC16(spq_u + (uint32_t)((row * ATPAD + col) * 2),
                   pq + gq + (size_t)row * DD + col);
    }
    CP_COMMIT();

    const float* kvp = g_kv + (size_t)bh * 4096;
    #pragma unroll
    for (int i = 0; i < 4; i++) {
        int lin = tid + i * 256;
        int d = lin >> 4, m4 = (lin & 15) * 4;
        float4 vv = *(const float4*)(kvp + d * 64 + m4);
        skvt[(m4 + 0) * ATPAD + d] = __float2half(vv.x);
        skvt[(m4 + 1) * ATPAD + d] = __float2half(vv.y);
        skvt[(m4 + 2) * ATPAD + d] = __float2half(vv.z);
        skvt[(m4 + 3) * ATPAD + d] = __float2half(vv.w);
    }
    if (tid < 64) sks[tid] = g_ksum[bh * 64 + tid];
    CP_WAIT(0);
    __syncthreads();

    if (tid < AT_TOK) {
        float dot = 0.0f;
        #pragma unroll
        for (int d = 0; d < 64; d++)
            dot += __half2float(spq[tid * ATPAD + d]) * sks[d];
        sz[tid] = 1.0f / (dot + ATTN_EPS);
    }
    __syncthreads();

    float acc[8][4];
    #pragma unroll
    for (int i = 0; i < 8; i++)
        #pragma unroll
        for (int j = 0; j < 4; j++) acc[i][j] = 0.0f;

    const uint32_t a_loff = (uint32_t)(
        ((16 * wid + (lane & 7) + (((lane >> 3) & 1) << 3)) * ATPAD + ((lane >> 4) << 3)) * 2);
    const uint32_t b_loff = (uint32_t)(
        (((lane & 7) + ((lane >> 4) << 3)) * ATPAD + (((lane >> 3) & 1) << 3)) * 2);

    #pragma unroll
    for (int k16 = 0; k16 < 4; k16++) {
        uint32_t a0, a1, a2, a3;
        LDSM_X4(a0, a1, a2, a3, spq_u + a_loff + (uint32_t)(k16 * 32));
        #pragma unroll
        for (int p = 0; p < 4; p++) {
            uint32_t r0, r1, r2, r3;
            LDSM_X4(r0, r1, r2, r3,
                    skv_u + b_loff + (uint32_t)(p * 16 * ATPAD * 2) + (uint32_t)(k16 * 32));
            mma_f16_16n8k16(acc[p * 2],     a0, a1, a2, a3, r0, r1);
            mma_f16_16n8k16(acc[p * 2 + 1], a0, a1, a2, a3, r2, r3);
        }
    }

    const int q = lane >> 2, r4 = lane & 3;
    const float z0 = sz[16 * wid + q];
    const float z1 = sz[16 * wid + q + 8];
    #pragma unroll
    for (int nt = 0; nt < 8; nt++) {
        int m = nt * 8 + 2 * r4;
        size_t row0 = (size_t)b * NN + t0 + 16 * wid + q;
        __half* op0 = out + row0 * DD + h * 64 + m;
        __half* op1 = out + (row0 + 8) * DD + h * 64 + m;
        *(__half2*)op0 = __floats2half2_rn(acc[nt][0] * z0, acc[nt][1] * z0);
        *(__half2*)op1 = __floats2half2_rn(acc[nt][2] * z1, acc[nt][3] * z1);
    }
}

// ---------------------------------------------------------------------------
// Combined weight transpose
// ---------------------------------------------------------------------------
struct TSeg { const float* src; __half* dst; int K; int N; int tile_base; };
struct TSegs { TSeg s[6]; int total; };

__global__ __launch_bounds__(256)
void transpose6_kernel(TSegs segs)
{
    __shared__ float tile[32][33];
    int bid = blockIdx.x;
    int si = 0;
    #pragma unroll
    for (int i = 1; i < 6; i++) if (bid >= segs.s[i].tile_base) si = i;
    const TSeg sg = segs.s[si];
    int tl = bid - sg.tile_base;
    int tiles_x = sg.K >> 5;
    int k0 = (tl % tiles_x) << 5;
    int n0 = (tl / tiles_x) << 5;

    int tx = threadIdx.x & 31, ty = threadIdx.x >> 5;
    #pragma unroll
    for (int i = 0; i < 32; i += 8)
        tile[ty + i][tx] = sg.src[(size_t)(k0 + ty + i) * sg.N + n0 + tx];
    __syncthreads();
    #pragma unroll
    for (int i = 0; i < 32; i += 8)
        sg.dst[(size_t)(n0 + ty + i) * sg.K + k0 + tx] = __float2half(tile[tx][ty + i]);
}

// ---------------------------------------------------------------------------
// prep: zero kv/ksum accumulators + concat qkv bias
// ---------------------------------------------------------------------------
__global__ void prep_kernel(const float* __restrict__ bq, const float* __restrict__ bk,
                            const float* __restrict__ bv)
{
    int idx = blockIdx.x * blockDim.x + threadIdx.x;
    const int NKV = BB * HH * DK * DV;
    const int NKS = BB * HH * DK;
    if (idx < NKV) g_kv[idx] = 0.0f;
    else if (idx < NKV + NKS) g_ksum[idx - NKV] = 0.0f;
    if (idx < 3 * DD) {
        float val = (idx < DD) ? bq[idx] : (idx < 2 * DD) ? bk[idx - DD] : bv[idx - 2 * DD];
        g_bqkv[idx] = val;
    }
}

// ---------------------------------------------------------------------------
// LayerNorm: warp-per-row (8 rows/block), fp32 or fp16 input, fp16 out
// ---------------------------------------------------------------------------
template<typename T>
__global__ __launch_bounds__(256)
void ln_kernel(const T* __restrict__ x, const float* __restrict__ g,
               const float* __restrict__ bta, __half* __restrict__ out)
{
    const int warp = threadIdx.x >> 5, lane = threadIdx.x & 31;
    const size_t row = (size_t)blockIdx.x * 8 + warp;

    float v[16];
    if (sizeof(T) == 4) {
        const float* xr = (const float*)x + row * DD;
        #pragma unroll
        for (int j = 0; j < 4; j++) {
            float4 t = *(const float4*)(xr + lane * 4 + j * 128);
            v[j * 4 + 0] = t.x; v[j * 4 + 1] = t.y;
            v[j * 4 + 2] = t.z; v[j * 4 + 3] = t.w;
        }
    } else {
        const __half* xr = (const __half*)x + row * DD;
        #pragma unroll
        for (int j = 0; j < 2; j++) {
            uint4 t = *(const uint4*)(xr + lane * 8 + j * 256);
            const __half2* hp = (const __half2*)&t;
            #pragma unroll
            for (int k = 0; k < 4; k++) {
                float2 f = __half22float2(hp[k]);
                v[j * 8 + 2 * k] = f.x; v[j * 8 + 2 * k + 1] = f.y;
            }
        }
    }

    float s = 0.0f;
    #pragma unroll
    for (int i = 0; i < 16; i++) s += v[i];
    #pragma unroll
    for (int o = 16; o; o >>= 1) s += __shfl_xor_sync(0xffffffffu, s, o);
    const float mean = s * (1.0f / DD);

    float qs = 0.0f;
    #pragma unroll
    for (int i = 0; i < 16; i++) { v[i] -= mean; qs += v[i] * v[i]; }
    #pragma unroll
    for (int o = 16; o; o >>= 1) qs += __shfl_xor_sync(0xffffffffu, qs, o);
    const float rs = rsqrtf(qs * (1.0f / DD) + LN_EPS);

    __half* orow = out + row * DD;
    if (sizeof(T) == 4) {
        #pragma unroll
        for (int j = 0; j < 4; j++) {
            int col = lane * 4 + j * 128;
            float4 gv = *(const float4*)(g + col);
            float4 bv = *(const float4*)(bta + col);
            *(__half2*)(orow + col)     = __floats2half2_rn(v[j*4+0] * rs * gv.x + bv.x,
                                                            v[j*4+1] * rs * gv.y + bv.y);
            *(__half2*)(orow + col + 2) = __floats2half2_rn(v[j*4+2] * rs * gv.z + bv.z,
                                                            v[j*4+3] * rs * gv.w + bv.w);
        }
    } else {
        #pragma unroll
        for (int j = 0; j < 2; j++) {
            int col = lane * 8 + j * 256;
            uint4 o4;
            __half2* op = (__half2*)&o4;
            #pragma unroll
            for (int k = 0; k < 4; k++) {
                float2 gv = *(const float2*)(g + col + 2 * k);
                float2 bv = *(const float2*)(bta + col + 2 * k);
                op[k] = __floats2half2_rn(v[j*8+2*k]   * rs * gv.x + bv.x,
                                          v[j*8+2*k+1] * rs * gv.y + bv.y);
            }
            *(uint4*)(orow + col) = o4;
        }
    }
}

// ---------------------------------------------------------------------------
// Launch
// ---------------------------------------------------------------------------
extern "C" void kernel_launch(void* const* d_in, const int* in_sizes, int n_in,
                              void* d_out, int out_size)
{
    const float* x     = (const float*)d_in[0];
    const float* ln1_g = (const float*)d_in[1];
    const float* ln1_b = (const float*)d_in[2];
    const float* Wq    = (const float*)d_in[3];
    const float* bq    = (const float*)d_in[4];
    const float* Wk    = (const float*)d_in[5];
    const float* bk    = (const float*)d_in[6];
    const float* Wv    = (const float*)d_in[7];
    const float* bv    = (const float*)d_in[8];
    const float* Wo    = (const float*)d_in[9];
    const float* bo    = (const float*)d_in[10];
    const float* ln2_g = (const float*)d_in[11];
    const float* ln2_b = (const float*)d_in[12];
    const float* W1    = (const float*)d_in[13];
    const float* b1    = (const float*)d_in[14];
    const float* W2    = (const float*)d_in[15];
    const float* b2    = (const float*)d_in[16];
    float* out = (float*)d_out;

    __half *p_h, *p_pq, *p_pk, *p_v, *p_attn, *p_hres, *p_h2, *p_act;
    __half *p_wqkvt, *p_wot, *p_w1t, *p_w2t;
    float *p_bqkv;
    cudaGetSymbolAddress((void**)&p_h,     g_h);
    cudaGetSymbolAddress((void**)&p_pq,    g_pq);
    cudaGetSymbolAddress((void**)&p_pk,    g_pk);
    cudaGetSymbolAddress((void**)&p_v,     g_v);
    cudaGetSymbolAddress((void**)&p_attn,  g_attn);
    cudaGetSymbolAddress((void**)&p_hres,  g_hres);
    cudaGetSymbolAddress((void**)&p_h2,    g_h2);
    cudaGetSymbolAddress((void**)&p_act,   g_act);
    cudaGetSymbolAddress((void**)&p_wqkvt, g_wqkvt);
    cudaGetSymbolAddress((void**)&p_wot,   g_wot);
    cudaGetSymbolAddress((void**)&p_w1t,   g_w1t);
    cudaGetSymbolAddress((void**)&p_w2t,   g_w2t);
    cudaGetSymbolAddress((void**)&p_bqkv,  g_bqkv);

    cudaFuncSetAttribute(mgemm_kernel<EPI_QKV , __half>, cudaFuncAttributeMaxDynamicSharedMemorySize, GEMM_SMEM);
    cudaFuncSetAttribute(mgemm_kernel<EPI_GELU, __half>, cudaFuncAttributeMaxDynamicSharedMemorySize, GEMM_SMEM);
    cudaFuncSetAttribute(mgemm_kernel<EPI_RES , __half>, cudaFuncAttributeMaxDynamicSharedMemorySize, GEMM_SMEM);
    cudaFuncSetAttribute(mgemm_kernel<EPI_RES , float >, cudaFuncAttributeMaxDynamicSharedMemorySize, GEMM_SMEM);
    cudaFuncSetAttribute(kvred_mma_kernel, cudaFuncAttributeMaxDynamicSharedMemorySize, KVRED_SMEM);

    // 0. weight transposes
    {
        TSegs segs;
        segs.s[0] = {Wq, p_wqkvt,                DD,  DD,  0};
        segs.s[1] = {Wk, p_wqkvt + DD * DD,      DD,  DD,  256};
        segs.s[2] = {Wv, p_wqkvt + 2 * DD * DD,  DD,  DD,  512};
        segs.s[3] = {Wo, p_wot,                  DD,  DD,  768};
        segs.s[4] = {W1, p_w1t,                  DD,  HID, 1024};
        segs.s[5] = {W2, p_w2t,                  HID, DD,  2048};
        segs.total = 3072;
        transpose6_kernel<<<3072, 256>>>(segs);
    }

    // 1. prep
    prep_kernel<<<(BB * HH * DK * DV + BB * HH * DK + 255) / 256, 256>>>(bq, bk, bv);

    // 2. LN1 (warp-per-row)
    ln_kernel<float><<<NTOK / 8, 256>>>(x, ln1_g, ln1_b, p_h);

    // 3. fused QKV projection
    mgemm_kernel<EPI_QKV, __half><<<dim3(3 * DD / BN, NTOK / BM), 256, GEMM_SMEM>>>(
        p_h, p_wqkvt, p_bqkv, nullptr, p_pq, p_pk, p_v, 3 * DD, DD);

    // 4. kv / ksum reduction (tensor cores)
    kvred_mma_kernel<<<dim3(BB * HH, NN / KVC), 256, KVRED_SMEM>>>(p_pk, p_v);

    // 5. attention apply (tensor cores)
    attn_mma_kernel<<<dim3(NN / AT_TOK, BB * HH), 256>>>(p_pq, p_attn);

    // 6. output projection + residual -> hres (fp16)
    mgemm_kernel<EPI_RES, __half><<<dim3(DD / BN, NTOK / BM), 256, GEMM_SMEM>>>(
        p_attn, p_wot, bo, p_h, p_hres, nullptr, nullptr, DD, DD);

    // 7. LN2 (warp-per-row, fp16 in)
    ln_kernel<__half><<<NTOK / 8, 256>>>(p_hres, ln2_g, ln2_b, p_h2);

    // 8. MLP up + gelu
    mgemm_kernel<EPI_GELU, __half><<<dim3(HID / BN, NTOK / BM), 256, GEMM_SMEM>>>(
        p_h2, p_w1t, b1, nullptr, p_act, nullptr, nullptr, HID, DD);

    // 9. MLP down + residual -> out (fp32)
    mgemm_kernel<EPI_RES, float><<<dim3(DD / BN, NTOK / BM), 256, GEMM_SMEM>>>(
        p_act, p_w2t, b2, p_h2, out, nullptr, nullptr, DD, HID);
}

// round 14
// speedup vs baseline: 1.0709x; 1.0709x over previous
#include <cuda_runtime.h>
#include <cuda_fp16.h>
#include <math.h>
#include <stdint.h>

// Problem constants
#define BB       4
#define NN       16384
#define DD       512
#define HH       8
#define DK       64
#define DV       64
#define HID      2048
#define NTOK     (BB * NN)          // 65536
#define LN_EPS   1e-5f
#define ATTN_EPS 1e-6f

// ---------------------------------------------------------------------------
// Scratch (device globals — no allocation allowed)
// ---------------------------------------------------------------------------
__device__ __half g_h   [(size_t)NTOK * DD];
__device__ __half g_pq  [(size_t)NTOK * DD];
__device__ __half g_pk  [(size_t)NTOK * DD];
__device__ __half g_v   [(size_t)NTOK * DD];
__device__ __half g_attn[(size_t)NTOK * DD];
__device__ __half g_hres[(size_t)NTOK * DD];
__device__ __half g_h2  [(size_t)NTOK * DD];
__device__ __half g_act [(size_t)NTOK * HID];
__device__ float  g_kv  [BB * HH * DK * DV];
__device__ float  g_ksum[BB * HH * DK];
__device__ __half g_wqkvt[3 * DD * DD];
__device__ __half g_wot[DD * DD];
__device__ __half g_w1t[(size_t)HID * DD];
__device__ __half g_w2t[(size_t)DD * HID];
__device__ float  g_bqkv[3 * DD];

// ---------------------------------------------------------------------------
// helpers
// ---------------------------------------------------------------------------
__device__ __forceinline__ uint32_t smem_u32(const void* p) {
    uint32_t a;
    asm("{ .reg .u64 t; cvta.to.shared.u64 t, %1; cvt.u32.u64 %0, t; }" : "=r"(a) : "l"(p));
    return a;
}

#define CP_ASYNC16(dst_u32, src) \
    asm volatile("cp.async.cg.shared.global [%0], [%1], 16;" :: "r"(dst_u32), "l"(src))
#define CP_COMMIT() asm volatile("cp.async.commit_group;" ::: "memory")
#define CP_WAIT(n)  asm volatile("cp.async.wait_group %0;" :: "n"(n) : "memory")

#define LDSM_X4T(r0, r1, r2, r3, addr) \
    asm volatile("ldmatrix.sync.aligned.m8n8.x4.trans.shared.b16 {%0,%1,%2,%3}, [%4];" \
        : "=r"(r0), "=r"(r1), "=r"(r2), "=r"(r3) : "r"(addr))
#define LDSM_X4(r0, r1, r2, r3, addr) \
    asm volatile("ldmatrix.sync.aligned.m8n8.x4.shared.b16 {%0,%1,%2,%3}, [%4];" \
        : "=r"(r0), "=r"(r1), "=r"(r2), "=r"(r3) : "r"(addr))

__device__ __forceinline__ void mma_f16_16n8k16(float c[4], uint32_t a0, uint32_t a1,
                                                uint32_t a2, uint32_t a3,
                                                uint32_t b0, uint32_t b1)
{
    asm volatile(
        "mma.sync.aligned.m16n8k16.row.col.f32.f16.f16.f32 "
        "{%0,%1,%2,%3}, {%4,%5,%6,%7}, {%8,%9}, {%0,%1,%2,%3};"
        : "+f"(c[0]), "+f"(c[1]), "+f"(c[2]), "+f"(c[3])
        : "r"(a0), "r"(a1), "r"(a2), "r"(a3), "r"(b0), "r"(b1));
}

// ---------------------------------------------------------------------------
// fp16 GEMM (R12 core — measured optimum): tile 128x128, BK=64,
// 3-stage cp.async (1 sync/kt), 8 warps 2Mx4N, double-buffered scalar-LDS
// fragments, 2 CTAs/SM
// ---------------------------------------------------------------------------
#define EPI_QKV  0
#define EPI_GELU 2
#define EPI_RES  3

#define BM      128
#define BN      128
#define BK      64
#define PADK    72
#define SA_H    (BM * PADK)
#define STG_H   (2 * SA_H)
#define NSTG    3
#define GEMM_SMEM (NSTG * STG_H * 2)     // 110592 bytes

__device__ __forceinline__ float gelu_tanh(float x) {
    float x3 = x * x * x;
    return 0.5f * x * (1.0f + tanhf(0.7978845608028654f * (x + 0.044715f * x3)));
}

template<int EPI, typename CT>
__global__ __launch_bounds__(256)
void mgemm_kernel(const __half* __restrict__ A, const __half* __restrict__ Bt,
                  const float* __restrict__ bias, const __half* __restrict__ resid,
                  CT* __restrict__ C, __half* __restrict__ C2, __half* __restrict__ C3,
                  int N, int K)
{
    extern __shared__ __half smem_h[];

    const int tid  = threadIdx.x;
    const int lane = tid & 31;
    const int wid  = tid >> 5;
    const int warpM = wid & 1;
    const int warpN = wid >> 1;

    const int mbase = blockIdx.y * BM;
    const int nbase = blockIdx.x * BN;

    const uint32_t s_u = smem_u32(smem_h);

    float acc[4][4][4];
    #pragma unroll
    for (int i = 0; i < 4; i++)
        #pragma unroll
        for (int j = 0; j < 4; j++)
            #pragma unroll
            for (int r = 0; r < 4; r++) acc[i][j][r] = 0.0f;

    const int T = K / BK;

    auto load_stage = [&](int kt, int st) {
        const int k0 = kt * BK;
        const uint32_t base = s_u + (uint32_t)(st * STG_H * 2);
        #pragma unroll
        for (int i = 0; i < 4; i++) {
            int linear = tid + i * 256;
            int row = linear >> 3;
            int col = (linear & 7) * 8;
            CP_ASYNC16(base + (uint32_t)((row * PADK + col) * 2),
                       A + (size_t)(mbase + row) * K + k0 + col);
            CP_ASYNC16(base + (uint32_t)((SA_H + row * PADK + col) * 2),
                       Bt + (size_t)(nbase + row) * K + k0 + col);
        }
    };

    load_stage(0, 0); CP_COMMIT();
    load_stage(1, 1); CP_COMMIT();

    const int q = lane >> 2, r4 = lane & 3;

    for (int kt = 0; kt < T; kt++) {
        CP_WAIT(1);
        __syncthreads();                 // stage kt%3 visible; kt-1 consumed last iter

        if (kt + 2 < T) load_stage(kt + 2, (kt + 2) % NSTG);
        CP_COMMIT();

        const __half* a_st = smem_h + (kt % NSTG) * STG_H;
        const __half* b_st = a_st + SA_H;

        uint32_t afr[2][4][4];
        uint32_t bfr[2][4][2];

        auto load_frag = [&](int ks, int buf) {
            const int kk = ks * 16;
            #pragma unroll
            for (int mt = 0; mt < 4; mt++) {
                const __half* ap = a_st + (warpM * 64 + mt * 16 + q) * PADK + kk + 2 * r4;
                afr[buf][mt][0] = *(const uint32_t*)(ap);
                afr[buf][mt][1] = *(const uint32_t*)(ap + 8 * PADK);
                afr[buf][mt][2] = *(const uint32_t*)(ap + 8);
                afr[buf][mt][3] = *(const uint32_t*)(ap + 8 * PADK + 8);
            }
            #pragma unroll
            for (int nt = 0; nt < 4; nt++) {
                const __half* bp = b_st + (warpN * 32 + nt * 8 + q) * PADK + kk + 2 * r4;
                bfr[buf][nt][0] = *(const uint32_t*)(bp);
                bfr[buf][nt][1] = *(const uint32_t*)(bp + 8);
            }
        };

        load_frag(0, 0);
        #pragma unroll
        for (int ks = 0; ks < 4; ks++) {
            if (ks < 3) load_frag(ks + 1, (ks + 1) & 1);
            const int b = ks & 1;
            #pragma unroll
            for (int mt = 0; mt < 4; mt++)
                #pragma unroll
                for (int nt = 0; nt < 4; nt++)
                    mma_f16_16n8k16(acc[mt][nt], afr[b][mt][0], afr[b][mt][1],
                                    afr[b][mt][2], afr[b][mt][3],
                                    bfr[b][nt][0], bfr[b][nt][1]);
        }
    }

    __half* qdst = nullptr;
    int ldc = N, cadj = 0;
    bool do_phi = false;
    if (EPI == EPI_QKV) {
        int sector = nbase >> 9;
        qdst = (sector == 0) ? (__half*)C : (sector == 1) ? C2 : C3;
        ldc = DD;
        cadj = sector << 9;
        do_phi = (sector < 2);
    }

    #pragma unroll
    for (int mt = 0; mt < 4; mt++) {
        #pragma unroll
        for (int nt = 0; nt < 4; nt++) {
            int col = nbase + warpN * 32 + nt * 8 + 2 * r4;
            float2 bv = *(const float2*)(bias + col);
            #pragma unroll
            for (int half_i = 0; half_i < 2; half_i++) {
                size_t row = (size_t)(mbase + warpM * 64 + mt * 16 + q + half_i * 8);
                float2 o;
                o.x = acc[mt][nt][half_i * 2 + 0] + bv.x;
                o.y = acc[mt][nt][half_i * 2 + 1] + bv.y;
                if (EPI == EPI_QKV) {
                    if (do_phi) {
                        o.x = (o.x > 0.0f) ? o.x + 1.0f : expf(o.x);
                        o.y = (o.y > 0.0f) ? o.y + 1.0f : expf(o.y);
                    }
                    *(__half2*)(qdst + row * ldc + (col - cadj)) = __floats2half2_rn(o.x, o.y);
                } else if (EPI == EPI_GELU) {
                    o.x = gelu_tanh(o.x);
                    o.y = gelu_tanh(o.y);
                    *(__half2*)((__half*)C + row * N + col) = __floats2half2_rn(o.x, o.y);
                } else { // EPI_RES
                    float2 rv = __half22float2(*(const __half2*)(resid + row * N + col));
                    o.x += rv.x; o.y += rv.y;
                    if (sizeof(CT) == 2)
                        *(__half2*)((__half*)C + row * N + col) = __floats2half2_rn(o.x, o.y);
                    else
                        *(float2*)((float*)C + row * N + col) = o;
                }
            }
        }
    }
}

// ---------------------------------------------------------------------------
// kvred via tensor cores (unchanged)
// ---------------------------------------------------------------------------
#define KVC       2048
#define KVSN      128
#define KVPAD     72
#define KV_SA     (KVSN * KVPAD)
#define KV_STG    (2 * KV_SA)
#define KV_NSTG   3
#define KVRED_SMEM (KV_NSTG * KV_STG * 2)

__global__ __launch_bounds__(256)
void kvred_mma_kernel(const __half* __restrict__ pk, const __half* __restrict__ v)
{
    extern __shared__ __half smem_h[];
    const int tid = threadIdx.x, lane = tid & 31, wid = tid >> 5;
    const int bh = blockIdx.x;
    const int b = bh >> 3, h = bh & 7;
    const int n0 = blockIdx.y * KVC;
    const uint32_t s_u = smem_u32(smem_h);

    const int d0 = (wid & 3) * 16;
    const int mhalf = (wid >> 2) * 32;

    float acc[4][4];
    #pragma unroll
    for (int i = 0; i < 4; i++)
        #pragma unroll
        for (int j = 0; j < 4; j++) acc[i][j] = 0.0f;
    float ks = 0.0f;

    const size_t gbase0 = ((size_t)b * NN + n0) * DD + h * 64;

    auto load_stage = [&](int s, int st) {
        const size_t gb = gbase0 + (size_t)s * KVSN * DD;
        const uint32_t sb = s_u + (uint32_t)(st * KV_STG * 2);
        #pragma unroll
        for (int i = 0; i < 8; i++) {
            int c = tid + i * 256;
            int arr = c >> 10;
            int row = (c >> 3) & 127;
            int col = (c & 7) * 8;
            const __half* src = (arr ? v : pk) + gb + (size_t)row * DD + col;
            CP_ASYNC16(sb + (uint32_t)((arr * KV_SA + row * KVPAD + col) * 2), src);
        }
    };

    load_stage(0, 0); CP_COMMIT();
    load_stage(1, 1); CP_COMMIT();

    const uint32_t a_loff = (uint32_t)(
        (((lane & 7) + ((lane >> 4) << 3)) * KVPAD + d0 + (((lane >> 3) & 1) << 3)) * 2);
    const uint32_t b_loff = (uint32_t)(
        (((lane & 7) + (((lane >> 3) & 1) << 3)) * KVPAD + mhalf + ((lane >> 4) << 3)) * 2);

    const int ksd = tid & 63, ksseg = tid >> 6;
    const int NSTAGES = KVC / KVSN;

    for (int s = 0; s < NSTAGES; s++) {
        CP_WAIT(1);
        __syncthreads();
        if (s + 2 < NSTAGES) load_stage(s + 2, (s + 2) % KV_NSTG);
        CP_COMMIT();

        const uint32_t pkb = s_u + (uint32_t)((s % KV_NSTG) * KV_STG * 2);
        const uint32_t vb  = pkb + (uint32_t)(KV_SA * 2);

        #pragma unroll
        for (int k16 = 0; k16 < KVSN / 16; k16++) {
            const uint32_t kofs = (uint32_t)(k16 * 16 * KVPAD * 2);
            uint32_t a0, a1, a2, a3;
            LDSM_X4T(a0, a1, a2, a3, pkb + kofs + a_loff);
            #pragma unroll
            for (int p = 0; p < 2; p++) {
                uint32_t r0, r1, r2, r3;
                LDSM_X4T(r0, r1, r2, r3, vb + kofs + b_loff + (uint32_t)(p * 32));
                mma_f16_16n8k16(acc[p * 2],     a0, a1, a2, a3, r0, r1);
                mma_f16_16n8k16(acc[p * 2 + 1], a0, a1, a2, a3, r2, r3);
            }
        }
        {
            const __half* pkp = smem_h + (s % KV_NSTG) * KV_STG
                              + (ksseg * 32) * KVPAD + ksd;
            #pragma unroll
            for (int r = 0; r < 32; r++)
                ks += __half2float(pkp[r * KVPAD]);
        }
    }

    const int q = lane >> 2, r4 = lane & 3;
    float* kvp = g_kv + (size_t)bh * 4096;
    #pragma unroll
    for (int nt = 0; nt < 4; nt++) {
        int m = mhalf + nt * 8 + 2 * r4;
        atomicAdd(&kvp[(d0 + q) * 64 + m],     acc[nt][0]);
        atomicAdd(&kvp[(d0 + q) * 64 + m + 1], acc[nt][1]);
        atomicAdd(&kvp[(d0 + q + 8) * 64 + m],     acc[nt][2]);
        atomicAdd(&kvp[(d0 + q + 8) * 64 + m + 1], acc[nt][3]);
    }
    atomicAdd(&g_ksum[bh * 64 + ksd], ks);
}

// ---------------------------------------------------------------------------
// attention apply via tensor cores (unchanged)
// ---------------------------------------------------------------------------
#define AT_TOK  128
#define ATPAD   72

__global__ __launch_bounds__(256)
void attn_mma_kernel(const __half* __restrict__ pq, __half* __restrict__ out)
{
    __shared__ __half spq[AT_TOK * ATPAD];
    __shared__ __half skvt[64 * ATPAD];
    __shared__ float sz[AT_TOK];
    __shared__ float sks[64];

    const int tid = threadIdx.x, lane = tid & 31, wid = tid >> 5;
    const int bh = blockIdx.y, b = bh >> 3, h = bh & 7;
    const int t0 = blockIdx.x * AT_TOK;
    const uint32_t spq_u = smem_u32(spq);
    const uint32_t skv_u = smem_u32(skvt);

    const size_t gq = ((size_t)b * NN + t0) * DD + h * 64;
    #pragma unroll
    for (int i = 0; i < 4; i++) {
        int c = tid + i * 256;
        int row = c >> 3, col = (c & 7) * 8;
        CP_ASYNC16(spq_u + (uint32_t)((row * ATPAD + col) * 2),
                   pq + gq + (size_t)row * DD + col);
    }
    CP_COMMIT();

    const float* kvp = g_kv + (size_t)bh * 4096;
    #pragma unroll
    for (int i = 0; i < 4; i++) {
        int lin = tid + i * 256;
        int d = lin >> 4, m4 = (lin & 15) * 4;
        float4 vv = *(const float4*)(kvp + d * 64 + m4);
        skvt[(m4 + 0) * ATPAD + d] = __float2half(vv.x);
        skvt[(m4 + 1) * ATPAD + d] = __float2half(vv.y);
        skvt[(m4 + 2) * ATPAD + d] = __float2half(vv.z);
        skvt[(m4 + 3) * ATPAD + d] = __float2half(vv.w);
    }
    if (tid < 64) sks[tid] = g_ksum[bh * 64 + tid];
    CP_WAIT(0);
    __syncthreads();

    if (tid < AT_TOK) {
        float dot = 0.0f;
        #pragma unroll
        for (int d = 0; d < 64; d++)
            dot += __half2float(spq[tid * ATPAD + d]) * sks[d];
        sz[tid] = 1.0f / (dot + ATTN_EPS);
    }
    __syncthreads();

    float acc[8][4];
    #pragma unroll
    for (int i = 0; i < 8; i++)
        #pragma unroll
        for (int j = 0; j < 4; j++) acc[i][j] = 0.0f;

    const uint32_t a_loff = (uint32_t)(
        ((16 * wid + (lane & 7) + (((lane >> 3) & 1) << 3)) * ATPAD + ((lane >> 4) << 3)) * 2);
    const uint32_t b_loff = (uint32_t)(
        (((lane & 7) + ((lane >> 4) << 3)) * ATPAD + (((lane >> 3) & 1) << 3)) * 2);

    #pragma unroll
    for (int k16 = 0; k16 < 4; k16++) {
        uint32_t a0, a1, a2, a3;
        LDSM_X4(a0, a1, a2, a3, spq_u + a_loff + (uint32_t)(k16 * 32));
        #pragma unroll
        for (int p = 0; p < 4; p++) {
            uint32_t r0, r1, r2, r3;
            LDSM_X4(r0, r1, r2, r3,
                    skv_u + b_loff + (uint32_t)(p * 16 * ATPAD * 2) + (uint32_t)(k16 * 32));
            mma_f16_16n8k16(acc[p * 2],     a0, a1, a2, a3, r0, r1);
            mma_f16_16n8k16(acc[p * 2 + 1], a0, a1, a2, a3, r2, r3);
        }
    }

    const int q = lane >> 2, r4 = lane & 3;
    const float z0 = sz[16 * wid + q];
    const float z1 = sz[16 * wid + q + 8];
    #pragma unroll
    for (int nt = 0; nt < 8; nt++) {
        int m = nt * 8 + 2 * r4;
        size_t row0 = (size_t)b * NN + t0 + 16 * wid + q;
        __half* op0 = out + row0 * DD + h * 64 + m;
        __half* op1 = out + (row0 + 8) * DD + h * 64 + m;
        *(__half2*)op0 = __floats2half2_rn(acc[nt][0] * z0, acc[nt][1] * z0);
        *(__half2*)op1 = __floats2half2_rn(acc[nt][2] * z1, acc[nt][3] * z1);
    }
}

// ---------------------------------------------------------------------------
// Combined weight transpose + prep (zero accumulators, concat bias)
// tiles [0, 3072): transpose; tile 3072..3079: prep work
// ---------------------------------------------------------------------------
struct TSeg { const float* src; __half* dst; int K; int N; int tile_base; };
struct TSegs {
    TSeg s[6];
    const float* bq; const float* bk; const float* bv;
};

__global__ __launch_bounds__(256)
void transpose6_kernel(TSegs segs)
{
    __shared__ float tile[32][33];
    int bid = blockIdx.x;

    if (bid >= 3072) {
        // prep: 8 blocks x 256 threads = 2048 threads cover kv+ksum+bias
        int idx = (bid - 3072) * 256 + threadIdx.x;
        const int NKV = BB * HH * DK * DV;      // 131072: strided by 2048
        for (int i = idx; i < NKV; i += 2048) g_kv[i] = 0.0f;
        if (idx < BB * HH * DK) g_ksum[idx] = 0.0f;
        if (idx < 3 * DD) {
            float val = (idx < DD) ? segs.bq[idx]
                      : (idx < 2 * DD) ? segs.bk[idx - DD] : segs.bv[idx - 2 * DD];
            g_bqkv[idx] = val;
        }
        return;
    }

    int si = 0;
    #pragma unroll
    for (int i = 1; i < 6; i++) if (bid >= segs.s[i].tile_base) si = i;
    const TSeg sg = segs.s[si];
    int tl = bid - sg.tile_base;
    int tiles_x = sg.K >> 5;
    int k0 = (tl % tiles_x) << 5;
    int n0 = (tl / tiles_x) << 5;

    int tx = threadIdx.x & 31, ty = threadIdx.x >> 5;
    #pragma unroll
    for (int i = 0; i < 32; i += 8)
        tile[ty + i][tx] = sg.src[(size_t)(k0 + ty + i) * sg.N + n0 + tx];
    __syncthreads();
    #pragma unroll
    for (int i = 0; i < 32; i += 8)
        sg.dst[(size_t)(n0 + ty + i) * sg.K + k0 + tx] = __float2half(tile[tx][ty + i]);
}

// ---------------------------------------------------------------------------
// LayerNorm: warp-per-row (8 rows/block), fp32 or fp16 input, fp16 out
// ---------------------------------------------------------------------------
template<typename T>
__global__ __launch_bounds__(256)
void ln_kernel(const T* __restrict__ x, const float* __restrict__ g,
               const float* __restrict__ bta, __half* __restrict__ out)
{
    const int warp = threadIdx.x >> 5, lane = threadIdx.x & 31;
    const size_t row = (size_t)blockIdx.x * 8 + warp;

    float v[16];
    if (sizeof(T) == 4) {
        const float* xr = (const float*)x + row * DD;
        #pragma unroll
        for (int j = 0; j < 4; j++) {
            float4 t = *(const float4*)(xr + lane * 4 + j * 128);
            v[j * 4 + 0] = t.x; v[j * 4 + 1] = t.y;
            v[j * 4 + 2] = t.z; v[j * 4 + 3] = t.w;
        }
    } else {
        const __half* xr = (const __half*)x + row * DD;
        #pragma unroll
        for (int j = 0; j < 2; j++) {
            uint4 t = *(const uint4*)(xr + lane * 8 + j * 256);
            const __half2* hp = (const __half2*)&t;
            #pragma unroll
            for (int k = 0; k < 4; k++) {
                float2 f = __half22float2(hp[k]);
                v[j * 8 + 2 * k] = f.x; v[j * 8 + 2 * k + 1] = f.y;
            }
        }
    }

    float s = 0.0f;
    #pragma unroll
    for (int i = 0; i < 16; i++) s += v[i];
    #pragma unroll
    for (int o = 16; o; o >>= 1) s += __shfl_xor_sync(0xffffffffu, s, o);
    const float mean = s * (1.0f / DD);

    float qs = 0.0f;
    #pragma unroll
    for (int i = 0; i < 16; i++) { v[i] -= mean; qs += v[i] * v[i]; }
    #pragma unroll
    for (int o = 16; o; o >>= 1) qs += __shfl_xor_sync(0xffffffffu, qs, o);
    const float rs = rsqrtf(qs * (1.0f / DD) + LN_EPS);

    __half* orow = out + row * DD;
    if (sizeof(T) == 4) {
        #pragma unroll
        for (int j = 0; j < 4; j++) {
            int col = lane * 4 + j * 128;
            float4 gv = *(const float4*)(g + col);
            float4 bv = *(const float4*)(bta + col);
            *(__half2*)(orow + col)     = __floats2half2_rn(v[j*4+0] * rs * gv.x + bv.x,
                                                            v[j*4+1] * rs * gv.y + bv.y);
            *(__half2*)(orow + col + 2) = __floats2half2_rn(v[j*4+2] * rs * gv.z + bv.z,
                                                            v[j*4+3] * rs * gv.w + bv.w);
        }
    } else {
        #pragma unroll
        for (int j = 0; j < 2; j++) {
            int col = lane * 8 + j * 256;
            uint4 o4;
            __half2* op = (__half2*)&o4;
            #pragma unroll
            for (int k = 0; k < 4; k++) {
                float2 gv = *(const float2*)(g + col + 2 * k);
                float2 bv = *(const float2*)(bta + col + 2 * k);
                op[k] = __floats2half2_rn(v[j*8+2*k]   * rs * gv.x + bv.x,
                                          v[j*8+2*k+1] * rs * gv.y + bv.y);
            }
            *(uint4*)(orow + col) = o4;
        }
    }
}

// ---------------------------------------------------------------------------
// Launch
// ---------------------------------------------------------------------------
extern "C" void kernel_launch(void* const* d_in, const int* in_sizes, int n_in,
                              void* d_out, int out_size)
{
    const float* x     = (const float*)d_in[0];
    const float* ln1_g = (const float*)d_in[1];
    const float* ln1_b = (const float*)d_in[2];
    const float* Wq    = (const float*)d_in[3];
    const float* bq    = (const float*)d_in[4];
    const float* Wk    = (const float*)d_in[5];
    const float* bk    = (const float*)d_in[6];
    const float* Wv    = (const float*)d_in[7];
    const float* bv    = (const float*)d_in[8];
    const float* Wo    = (const float*)d_in[9];
    const float* bo    = (const float*)d_in[10];
    const float* ln2_g = (const float*)d_in[11];
    const float* ln2_b = (const float*)d_in[12];
    const float* W1    = (const float*)d_in[13];
    const float* b1    = (const float*)d_in[14];
    const float* W2    = (const float*)d_in[15];
    const float* b2    = (const float*)d_in[16];
    float* out = (float*)d_out;

    __half *p_h, *p_pq, *p_pk, *p_v, *p_attn, *p_hres, *p_h2, *p_act;
    __half *p_wqkvt, *p_wot, *p_w1t, *p_w2t;
    float *p_bqkv;
    cudaGetSymbolAddress((void**)&p_h,     g_h);
    cudaGetSymbolAddress((void**)&p_pq,    g_pq);
    cudaGetSymbolAddress((void**)&p_pk,    g_pk);
    cudaGetSymbolAddress((void**)&p_v,     g_v);
    cudaGetSymbolAddress((void**)&p_attn,  g_attn);
    cudaGetSymbolAddress((void**)&p_hres,  g_hres);
    cudaGetSymbolAddress((void**)&p_h2,    g_h2);
    cudaGetSymbolAddress((void**)&p_act,   g_act);
    cudaGetSymbolAddress((void**)&p_wqkvt, g_wqkvt);
    cudaGetSymbolAddress((void**)&p_wot,   g_wot);
    cudaGetSymbolAddress((void**)&p_w1t,   g_w1t);
    cudaGetSymbolAddress((void**)&p_w2t,   g_w2t);
    cudaGetSymbolAddress((void**)&p_bqkv,  g_bqkv);

    cudaFuncSetAttribute(mgemm_kernel<EPI_QKV , __half>, cudaFuncAttributeMaxDynamicSharedMemorySize, GEMM_SMEM);
    cudaFuncSetAttribute(mgemm_kernel<EPI_GELU, __half>, cudaFuncAttributeMaxDynamicSharedMemorySize, GEMM_SMEM);
    cudaFuncSetAttribute(mgemm_kernel<EPI_RES , __half>, cudaFuncAttributeMaxDynamicSharedMemorySize, GEMM_SMEM);
    cudaFuncSetAttribute(mgemm_kernel<EPI_RES , float >, cudaFuncAttributeMaxDynamicSharedMemorySize, GEMM_SMEM);
    cudaFuncSetAttribute(kvred_mma_kernel, cudaFuncAttributeMaxDynamicSharedMemorySize, KVRED_SMEM);

    // 0. weight transposes + prep (one kernel)
    {
        TSegs segs;
        segs.s[0] = {Wq, p_wqkvt,                DD,  DD,  0};
        segs.s[1] = {Wk, p_wqkvt + DD * DD,      DD,  DD,  256};
        segs.s[2] = {Wv, p_wqkvt + 2 * DD * DD,  DD,  DD,  512};
        segs.s[3] = {Wo, p_wot,                  DD,  DD,  768};
        segs.s[4] = {W1, p_w1t,                  DD,  HID, 1024};
        segs.s[5] = {W2, p_w2t,                  HID, DD,  2048};
        segs.bq = bq; segs.bk = bk; segs.bv = bv;
        transpose6_kernel<<<3072 + 8, 256>>>(segs);
    }

    // 1. LN1 (warp-per-row)
    ln_kernel<float><<<NTOK / 8, 256>>>(x, ln1_g, ln1_b, p_h);

    // 2. fused QKV projection
    mgemm_kernel<EPI_QKV, __half><<<dim3(3 * DD / BN, NTOK / BM), 256, GEMM_SMEM>>>(
        p_h, p_wqkvt, p_bqkv, nullptr, p_pq, p_pk, p_v, 3 * DD, DD);

    // 3. kv / ksum reduction (tensor cores)
    kvred_mma_kernel<<<dim3(BB * HH, NN / KVC), 256, KVRED_SMEM>>>(p_pk, p_v);

    // 4. attention apply (tensor cores)
    attn_mma_kernel<<<dim3(NN / AT_TOK, BB * HH), 256>>>(p_pq, p_attn);

    // 5. output projection + residual -> hres (fp16)
    mgemm_kernel<EPI_RES, __half><<<dim3(DD / BN, NTOK / BM), 256, GEMM_SMEM>>>(
        p_attn, p_wot, bo, p_h, p_hres, nullptr, nullptr, DD, DD);

    // 6. LN2 (warp-per-row, fp16 in)
    ln_kernel<__half><<<NTOK / 8, 256>>>(p_hres, ln2_g, ln2_b, p_h2);

    // 7. MLP up + gelu
    mgemm_kernel<EPI_GELU, __half><<<dim3(HID / BN, NTOK / BM), 256, GEMM_SMEM>>>(
        p_h2, p_w1t, b1, nullptr, p_act, nullptr, nullptr, HID, DD);

    // 8. MLP down + residual -> out (fp32)
    mgemm_kernel<EPI_RES, float><<<dim3(DD / BN, NTOK / BM), 256, GEMM_SMEM>>>(
        p_act, p_w2t, b2, p_h2, out, nullptr, nullptr, DD, HID);
}